// round 6
// baseline (speedup 1.0000x reference)
#include <cuda_runtime.h>
#include <cuda_bf16.h>
#include <stdint.h>

// Problem constants
#define BB 16
#define NN 8192
#define DD 256
#define HH 128
#define NP 64
#define KSEL 32
#define ROWS (BB * NN)          // 131072
#define SEL_PER_B (NP * KSEL)   // 2048

// ---- bf16 pack/extract helpers ----
__device__ __forceinline__ uint32_t pack_bf16x2(float x, float y) {
    uint32_t r;
    asm("cvt.rn.bf16x2.f32 %0, %1, %2;" : "=r"(r) : "f"(y), "f"(x));
    return r;
}
__device__ __forceinline__ float bf_lo(uint32_t p) { return __uint_as_float(p << 16); }
__device__ __forceinline__ float bf_hi(uint32_t p) { return __uint_as_float(p & 0xFFFF0000u); }

__device__ __forceinline__ void mma_bf16(float c[4],
                                         uint32_t a0, uint32_t a1, uint32_t a2, uint32_t a3,
                                         uint32_t b0, uint32_t b1) {
    asm volatile(
        "mma.sync.aligned.m16n8k16.row.col.f32.bf16.bf16.f32 "
        "{%0,%1,%2,%3}, {%4,%5,%6,%7}, {%8,%9}, {%0,%1,%2,%3};"
        : "+f"(c[0]), "+f"(c[1]), "+f"(c[2]), "+f"(c[3])
        : "r"(a0), "r"(a1), "r"(a2), "r"(a3), "r"(b0), "r"(b1));
}

__device__ __forceinline__ uint32_t smem_u32(const void* p) {
    uint32_t a;
    asm("{ .reg .u64 t; cvta.to.shared.u64 t, %1; cvt.u32.u64 %0, t; }" : "=r"(a) : "l"(p));
    return a;
}
__device__ __forceinline__ void cp_async16(uint32_t dst, const void* src) {
    asm volatile("cp.async.cg.shared.global [%0], [%1], 16;" :: "r"(dst), "l"(src));
}
#define CP_COMMIT() asm volatile("cp.async.commit_group;")
#define CP_WAIT0()  asm volatile("cp.async.wait_group 0;")

// W1 split into 2 bf16 planes, mma B-fragment layout:
// g_Bf[kt][nt][plane][lane] = uint2 {b0, b1}
__device__ uint2 g_Bf[16][16][2][32];

// ============================================================
// K0: build split W1 fragment table
// ============================================================
__global__ void k_prepB(const float* __restrict__ W1)
{
    int idx  = blockIdx.x * 256 + threadIdx.x;   // 0..16383
    int lane = idx & 31;
    int pl   = (idx >> 5) & 1;
    int nt   = (idx >> 6) & 15;
    int kt   = idx >> 10;

    int k0 = kt * 16 + (lane & 3) * 2;
    int n  = nt * 8 + (lane >> 2);

    uint32_t reg[2];
#pragma unroll
    for (int r = 0; r < 2; r++) {
        int k = k0 + r * 8;
        float v0 = W1[(size_t)k * HH + n];
        float v1 = W1[(size_t)(k + 1) * HH + n];
        uint32_t h = pack_bf16x2(v0, v1);
        reg[r] = (pl == 0) ? h : pack_bf16x2(v0 - bf_lo(h), v1 - bf_hi(h));
    }
    g_Bf[kt][nt][pl][lane] = make_uint2(reg[0], reg[1]);
}

// ============================================================
// K1: logits = relu(features @ W1 + b1) @ W2 + b2
// Split-bf16 mma.sync (4 products). CTA: 128 rows x 128 cols,
// 4 warps (2 wm x 2 wn), warp tile 64x64. B double-buffered in
// smem via cp.async; A raw floats software-pipelined in regs.
// ============================================================
__global__ __launch_bounds__(128, 2)
void k_logits_tc(const float* __restrict__ features,
                 const float* __restrict__ b1,
                 const float* __restrict__ W2,
                 const float* __restrict__ b2,
                 float* __restrict__ logits)
{
    __shared__ uint2 sB[2][16][2][32];        // [buf][nt][plane][lane]
    __shared__ float s_b1[HH], s_w2[HH];
    __shared__ float s_red[128][2];

    const int tid  = threadIdx.x;
    const int wid  = tid >> 5;
    const int lane = tid & 31;
    const int wm   = wid >> 1;       // 0..1
    const int wn   = wid & 1;        // 0..1
    const int g    = lane >> 2;      // 0..7
    const int tig  = lane & 3;       // 0..3
    const int row0 = blockIdx.x * 128;

    if (tid < HH) { s_b1[tid] = b1[tid]; s_w2[tid] = W2[tid]; }

    // prefetch B for kt=0
    {
        const char* src = (const char*)&g_Bf[0][0][0][0];
        uint32_t dst = smem_u32(&sB[0][0][0][0]);
#pragma unroll
        for (int i = 0; i < 4; i++) {
            int c = tid + 128 * i;
            cp_async16(dst + c * 16, src + c * 16);
        }
        CP_COMMIT();
    }

    float acc[4][8][4];
#pragma unroll
    for (int mt = 0; mt < 4; mt++)
#pragma unroll
        for (int nt = 0; nt < 8; nt++)
#pragma unroll
            for (int c = 0; c < 4; c++) acc[mt][nt][c] = 0.0f;

    const float* Abase = features + (size_t)row0 * DD;
    const int rg = wm * 64 + g;
    const int kcol = tig * 2;

    // prologue: raw A for kt=0
    float2 Av[4][4], Avn[4][4];
#pragma unroll
    for (int mt = 0; mt < 4; mt++) {
        const float* Ar0 = Abase + (size_t)(rg + mt * 16) * DD + kcol;
        const float* Ar1 = Ar0 + 8 * DD;
        Av[mt][0] = *(const float2*)(Ar0);
        Av[mt][1] = *(const float2*)(Ar1);
        Av[mt][2] = *(const float2*)(Ar0 + 8);
        Av[mt][3] = *(const float2*)(Ar1 + 8);
    }

    for (int kt = 0; kt < 16; kt++) {
        const int buf = kt & 1;
        CP_WAIT0();
        __syncthreads();
        if (kt < 15) {
            // B prefetch (smem) for kt+1
            const char* src = (const char*)&g_Bf[kt + 1][0][0][0];
            uint32_t dst = smem_u32(&sB[buf ^ 1][0][0][0]);
#pragma unroll
            for (int i = 0; i < 4; i++) {
                int c = tid + 128 * i;
                cp_async16(dst + c * 16, src + c * 16);
            }
            CP_COMMIT();
            // A register prefetch for kt+1 (LDGs in flight under convert+MMA)
            const int k0n = (kt + 1) * 16 + kcol;
#pragma unroll
            for (int mt = 0; mt < 4; mt++) {
                const float* Ar0 = Abase + (size_t)(rg + mt * 16) * DD + k0n;
                const float* Ar1 = Ar0 + 8 * DD;
                Avn[mt][0] = *(const float2*)(Ar0);
                Avn[mt][1] = *(const float2*)(Ar1);
                Avn[mt][2] = *(const float2*)(Ar0 + 8);
                Avn[mt][3] = *(const float2*)(Ar1 + 8);
            }
        }

        // convert current A to split fragments
        uint32_t Ah[4][4], Al[4][4];
#pragma unroll
        for (int mt = 0; mt < 4; mt++) {
#pragma unroll
            for (int q = 0; q < 4; q++) {
                float2 v = Av[mt][q];
                uint32_t h = pack_bf16x2(v.x, v.y);
                Ah[mt][q] = h;
                Al[mt][q] = pack_bf16x2(v.x - bf_lo(h), v.y - bf_hi(h));
            }
        }

#pragma unroll
        for (int nt = 0; nt < 8; nt++) {
            const int ntg = wn * 8 + nt;
            uint2 bh = sB[buf][ntg][0][lane];
            uint2 bl = sB[buf][ntg][1][lane];
#pragma unroll
            for (int mt = 0; mt < 4; mt++) {
                mma_bf16(acc[mt][nt], Ah[mt][0], Ah[mt][1], Ah[mt][2], Ah[mt][3], bh.x, bh.y);
                mma_bf16(acc[mt][nt], Ah[mt][0], Ah[mt][1], Ah[mt][2], Ah[mt][3], bl.x, bl.y);
                mma_bf16(acc[mt][nt], Al[mt][0], Al[mt][1], Al[mt][2], Al[mt][3], bh.x, bh.y);
                mma_bf16(acc[mt][nt], Al[mt][0], Al[mt][1], Al[mt][2], Al[mt][3], bl.x, bl.y);
            }
        }

#pragma unroll
        for (int mt = 0; mt < 4; mt++)
#pragma unroll
            for (int q = 0; q < 4; q++)
                Av[mt][q] = Avn[mt][q];
    }

    // Epilogue: relu(c + b1) * W2, reduce over hidden
    float rs[8];
#pragma unroll
    for (int i = 0; i < 8; i++) rs[i] = 0.0f;
#pragma unroll
    for (int nt = 0; nt < 8; nt++) {
        const int c = wn * 64 + nt * 8 + tig * 2;
        float bb0 = s_b1[c],     w0 = s_w2[c];
        float bb1 = s_b1[c + 1], w1 = s_w2[c + 1];
#pragma unroll
        for (int mt = 0; mt < 4; mt++) {
            float x0 = acc[mt][nt][0] + bb0; x0 = x0 > 0.0f ? x0 : 0.0f;
            float x1 = acc[mt][nt][1] + bb1; x1 = x1 > 0.0f ? x1 : 0.0f;
            float x2 = acc[mt][nt][2] + bb0; x2 = x2 > 0.0f ? x2 : 0.0f;
            float x3 = acc[mt][nt][3] + bb1; x3 = x3 > 0.0f ? x3 : 0.0f;
            rs[2 * mt + 0] += x0 * w0 + x1 * w1;
            rs[2 * mt + 1] += x2 * w0 + x3 * w1;
        }
    }
#pragma unroll
    for (int off = 1; off <= 2; off <<= 1)
#pragma unroll
        for (int i = 0; i < 8; i++)
            rs[i] += __shfl_xor_sync(0xFFFFFFFFu, rs[i], off);

    if (tig == 0) {
#pragma unroll
        for (int mt = 0; mt < 4; mt++) {
            s_red[wm * 64 + mt * 16 + g][wn]     = rs[2 * mt + 0];
            s_red[wm * 64 + mt * 16 + g + 8][wn] = rs[2 * mt + 1];
        }
    }
    __syncthreads();
    if (tid < 128)
        logits[(size_t)row0 + tid] = s_red[tid][0] + s_red[tid][1] + __ldg(b2);
}

// ============================================================
// K2: per (batch, parcel) top-32 of z = logits + gumbel.
// ============================================================
__global__ void k_select(const float* __restrict__ logits,
                         const float* __restrict__ gumbel,
                         float* __restrict__ out_idx)
{
    const int g = blockIdx.x * (blockDim.x >> 5) + (threadIdx.x >> 5);
    const int lane = threadIdx.x & 31;
    const int b = g >> 6;
    const int p = g & 63;
    const float NEG_INF = __int_as_float(0xff800000);

    float v[4];
    int nidx[4];
#pragma unroll
    for (int q = 0; q < 4; q++) {
        int n = p + 64 * (lane + 32 * q);
        size_t off = (size_t)b * NN + n;
        v[q] = logits[off] + gumbel[off];
        nidx[q] = n;
    }

    for (int it = 0; it < KSEL; it++) {
        float bv = v[0]; int bn = nidx[0];
#pragma unroll
        for (int q = 1; q < 4; q++)
            if (v[q] > bv || (v[q] == bv && nidx[q] < bn)) { bv = v[q]; bn = nidx[q]; }
#pragma unroll
        for (int off = 16; off; off >>= 1) {
            float ov = __shfl_xor_sync(0xFFFFFFFFu, bv, off);
            int   on = __shfl_xor_sync(0xFFFFFFFFu, bn, off);
            if (ov > bv || (ov == bv && on < bn)) { bv = ov; bn = on; }
        }
        if (lane == 0)
            out_idx[(size_t)b * SEL_PER_B + p * KSEL + it] = (float)bn;
#pragma unroll
        for (int q = 0; q < 4; q++)
            if (nidx[q] == bn) v[q] = NEG_INF;
    }
}

// ============================================================
// K3: gather selected patch rows (warp per row).
// ============================================================
__global__ __launch_bounds__(256)
void k_gather(const float* __restrict__ patches,
              const float* __restrict__ out_idx,
              float* __restrict__ out_sel)
{
    const int gw = blockIdx.x * 8 + (threadIdx.x >> 5);
    const int lane = threadIdx.x & 31;
    const int b = gw >> 11;
    const int j = gw & 2047;
    const int n = (int)out_idx[(size_t)b * SEL_PER_B + j];
    const float4* src = (const float4*)&patches[((size_t)b * NN + n) * DD];
    float4* dst = (float4*)&out_sel[((size_t)b * SEL_PER_B + j) * DD];
    dst[lane]      = src[lane];
    dst[lane + 32] = src[lane + 32];
}

// ============================================================
// launch
// ============================================================
extern "C" void kernel_launch(void* const* d_in, const int* in_sizes, int n_in,
                              void* d_out, int out_size)
{
    const float* patches  = (const float*)d_in[0];
    const float* features = (const float*)d_in[1];
    const float* W1       = (const float*)d_in[2];
    const float* b1       = (const float*)d_in[3];
    const float* W2       = (const float*)d_in[4];
    const float* b2       = (const float*)d_in[5];
    const float* gumbel   = (const float*)d_in[6];

    float* out      = (float*)d_out;
    float* out_sel  = out;                                 // [B, 2048, 256]
    float* out_idx  = out + (size_t)BB * SEL_PER_B * DD;   // [B, 2048]
    float* out_log  = out_idx + (size_t)BB * SEL_PER_B;    // [B, N]

    k_prepB<<<64, 256>>>(W1);
    k_logits_tc<<<ROWS / 128, 128>>>(features, b1, W2, b2, out_log);
    k_select<<<(BB * NP) / 8, 256>>>(out_log, gumbel, out_idx);
    k_gather<<<BB * SEL_PER_B / 8, 256>>>(patches, out_idx, out_sel);
}

// round 7
// speedup vs baseline: 1.1821x; 1.1821x over previous
#include <cuda_runtime.h>
#include <cuda_bf16.h>
#include <stdint.h>

// Problem constants
#define BB 16
#define NN 8192
#define DD 256
#define HH 128
#define NP 64
#define KSEL 32
#define ROWS (BB * NN)          // 131072
#define SEL_PER_B (NP * KSEL)   // 2048

// ---- bf16 pack/extract helpers ----
__device__ __forceinline__ uint32_t pack_bf16x2(float x, float y) {
    uint32_t r;
    asm("cvt.rn.bf16x2.f32 %0, %1, %2;" : "=r"(r) : "f"(y), "f"(x));
    return r;
}
__device__ __forceinline__ float bf_lo(uint32_t p) { return __uint_as_float(p << 16); }
__device__ __forceinline__ float bf_hi(uint32_t p) { return __uint_as_float(p & 0xFFFF0000u); }

__device__ __forceinline__ void mma_bf16(float c[4],
                                         uint32_t a0, uint32_t a1, uint32_t a2, uint32_t a3,
                                         uint32_t b0, uint32_t b1) {
    asm volatile(
        "mma.sync.aligned.m16n8k16.row.col.f32.bf16.bf16.f32 "
        "{%0,%1,%2,%3}, {%4,%5,%6,%7}, {%8,%9}, {%0,%1,%2,%3};"
        : "+f"(c[0]), "+f"(c[1]), "+f"(c[2]), "+f"(c[3])
        : "r"(a0), "r"(a1), "r"(a2), "r"(a3), "r"(b0), "r"(b1));
}

__device__ __forceinline__ uint32_t smem_u32(const void* p) {
    uint32_t a;
    asm("{ .reg .u64 t; cvta.to.shared.u64 t, %1; cvt.u32.u64 %0, t; }" : "=r"(a) : "l"(p));
    return a;
}
__device__ __forceinline__ void cp_async16(uint32_t dst, const void* src) {
    asm volatile("cp.async.cg.shared.global [%0], [%1], 16;" :: "r"(dst), "l"(src));
}
__device__ __forceinline__ void cp_async8(uint32_t dst, const void* src) {
    asm volatile("cp.async.ca.shared.global [%0], [%1], 8;" :: "r"(dst), "l"(src));
}
#define CP_COMMIT() asm volatile("cp.async.commit_group;")
#define CP_WAIT0()  asm volatile("cp.async.wait_group 0;")

// W1 split into 2 bf16 planes, mma B-fragment layout:
// g_Bf[kt][nt][plane][lane] = uint2 {b0, b1}
__device__ uint2 g_Bf[16][16][2][32];

// ============================================================
// K0: build split W1 fragment table
// ============================================================
__global__ void k_prepB(const float* __restrict__ W1)
{
    int idx  = blockIdx.x * 256 + threadIdx.x;   // 0..16383
    int lane = idx & 31;
    int pl   = (idx >> 5) & 1;
    int nt   = (idx >> 6) & 15;
    int kt   = idx >> 10;

    int k0 = kt * 16 + (lane & 3) * 2;
    int n  = nt * 8 + (lane >> 2);

    uint32_t reg[2];
#pragma unroll
    for (int r = 0; r < 2; r++) {
        int k = k0 + r * 8;
        float v0 = W1[(size_t)k * HH + n];
        float v1 = W1[(size_t)(k + 1) * HH + n];
        uint32_t h = pack_bf16x2(v0, v1);
        reg[r] = (pl == 0) ? h : pack_bf16x2(v0 - bf_lo(h), v1 - bf_hi(h));
    }
    g_Bf[kt][nt][pl][lane] = make_uint2(reg[0], reg[1]);
}

// ============================================================
// K1: logits = relu(features @ W1 + b1) @ W2 + b2
// Split-bf16 mma.sync (4 products). CTA: 128 rows x 128 cols,
// 4 warps (2 wm x 2 wn), warp tile 64x64.
// A AND B double-buffered in smem via cp.async (2-stage).
// ============================================================
#define ASTRIDE 18   // floats per A smem row (pad vs 16 to soften bank conflicts)

__global__ __launch_bounds__(128, 2)
void k_logits_tc(const float* __restrict__ features,
                 const float* __restrict__ b1,
                 const float* __restrict__ W2,
                 const float* __restrict__ b2,
                 float* __restrict__ logits)
{
    __shared__ float sA[2][128][ASTRIDE];     // 18432 B
    __shared__ uint2 sB[2][16][2][32];        // 16384 B
    __shared__ float s_b1[HH], s_w2[HH];
    __shared__ float s_red[128][2];

    const int tid  = threadIdx.x;
    const int wid  = tid >> 5;
    const int lane = tid & 31;
    const int wm   = wid >> 1;       // 0..1
    const int wn   = wid & 1;        // 0..1
    const int g    = lane >> 2;      // 0..7
    const int tig  = lane & 3;       // 0..3
    const int row0 = blockIdx.x * 128;

    if (tid < HH) { s_b1[tid] = b1[tid]; s_w2[tid] = W2[tid]; }

    const float* Abase = features + (size_t)row0 * DD;

    // ---- stage prefetch helper (A: 8 chunks of 8B; B: 4 chunks of 16B) ----
    auto prefetch = [&](int stage, int kt) {
        // A slab: 128 rows x 16 floats at k-offset kt*16
        const int koff = kt * 16;
#pragma unroll
        for (int i = 0; i < 8; i++) {
            int cidx = tid + 128 * i;         // 0..1023
            int r = cidx >> 3;
            int c = cidx & 7;                 // 8B chunk (2 floats)
            cp_async8(smem_u32(&sA[stage][r][c * 2]),
                      Abase + (size_t)r * DD + koff + c * 2);
        }
        // B slab
        const char* src = (const char*)&g_Bf[kt][0][0][0];
        uint32_t dst = smem_u32(&sB[stage][0][0][0]);
#pragma unroll
        for (int i = 0; i < 4; i++) {
            int c = tid + 128 * i;
            cp_async16(dst + c * 16, src + c * 16);
        }
        CP_COMMIT();
    };

    prefetch(0, 0);

    float acc[4][8][4];
#pragma unroll
    for (int mt = 0; mt < 4; mt++)
#pragma unroll
        for (int nt = 0; nt < 8; nt++)
#pragma unroll
            for (int c = 0; c < 4; c++) acc[mt][nt][c] = 0.0f;

    const int rg = wm * 64 + g;
    const int kcol = tig * 2;

    for (int kt = 0; kt < 16; kt++) {
        const int buf = kt & 1;
        CP_WAIT0();
        __syncthreads();
        if (kt < 15) prefetch(buf ^ 1, kt + 1);

        // convert A from smem to split fragments
        uint32_t Ah[4][4], Al[4][4];
#pragma unroll
        for (int mt = 0; mt < 4; mt++) {
            const int r0 = rg + mt * 16;
            float2 v00 = *(const float2*)&sA[buf][r0][kcol];
            float2 v10 = *(const float2*)&sA[buf][r0 + 8][kcol];
            float2 v01 = *(const float2*)&sA[buf][r0][kcol + 8];
            float2 v11 = *(const float2*)&sA[buf][r0 + 8][kcol + 8];
            Ah[mt][0] = pack_bf16x2(v00.x, v00.y);
            Ah[mt][1] = pack_bf16x2(v10.x, v10.y);
            Ah[mt][2] = pack_bf16x2(v01.x, v01.y);
            Ah[mt][3] = pack_bf16x2(v11.x, v11.y);
            Al[mt][0] = pack_bf16x2(v00.x - bf_lo(Ah[mt][0]), v00.y - bf_hi(Ah[mt][0]));
            Al[mt][1] = pack_bf16x2(v10.x - bf_lo(Ah[mt][1]), v10.y - bf_hi(Ah[mt][1]));
            Al[mt][2] = pack_bf16x2(v01.x - bf_lo(Ah[mt][2]), v01.y - bf_hi(Ah[mt][2]));
            Al[mt][3] = pack_bf16x2(v11.x - bf_lo(Ah[mt][3]), v11.y - bf_hi(Ah[mt][3]));
        }

#pragma unroll
        for (int nt = 0; nt < 8; nt++) {
            const int ntg = wn * 8 + nt;
            uint2 bh = sB[buf][ntg][0][lane];
            uint2 bl = sB[buf][ntg][1][lane];
#pragma unroll
            for (int mt = 0; mt < 4; mt++) {
                mma_bf16(acc[mt][nt], Ah[mt][0], Ah[mt][1], Ah[mt][2], Ah[mt][3], bh.x, bh.y);
                mma_bf16(acc[mt][nt], Ah[mt][0], Ah[mt][1], Ah[mt][2], Ah[mt][3], bl.x, bl.y);
                mma_bf16(acc[mt][nt], Al[mt][0], Al[mt][1], Al[mt][2], Al[mt][3], bh.x, bh.y);
                mma_bf16(acc[mt][nt], Al[mt][0], Al[mt][1], Al[mt][2], Al[mt][3], bl.x, bl.y);
            }
        }
    }

    // Epilogue: relu(c + b1) * W2, reduce over hidden
    float rs[8];
#pragma unroll
    for (int i = 0; i < 8; i++) rs[i] = 0.0f;
#pragma unroll
    for (int nt = 0; nt < 8; nt++) {
        const int c = wn * 64 + nt * 8 + tig * 2;
        float bb0 = s_b1[c],     w0 = s_w2[c];
        float bb1 = s_b1[c + 1], w1 = s_w2[c + 1];
#pragma unroll
        for (int mt = 0; mt < 4; mt++) {
            float x0 = acc[mt][nt][0] + bb0; x0 = x0 > 0.0f ? x0 : 0.0f;
            float x1 = acc[mt][nt][1] + bb1; x1 = x1 > 0.0f ? x1 : 0.0f;
            float x2 = acc[mt][nt][2] + bb0; x2 = x2 > 0.0f ? x2 : 0.0f;
            float x3 = acc[mt][nt][3] + bb1; x3 = x3 > 0.0f ? x3 : 0.0f;
            rs[2 * mt + 0] += x0 * w0 + x1 * w1;
            rs[2 * mt + 1] += x2 * w0 + x3 * w1;
        }
    }
#pragma unroll
    for (int off = 1; off <= 2; off <<= 1)
#pragma unroll
        for (int i = 0; i < 8; i++)
            rs[i] += __shfl_xor_sync(0xFFFFFFFFu, rs[i], off);

    if (tig == 0) {
#pragma unroll
        for (int mt = 0; mt < 4; mt++) {
            s_red[wm * 64 + mt * 16 + g][wn]     = rs[2 * mt + 0];
            s_red[wm * 64 + mt * 16 + g + 8][wn] = rs[2 * mt + 1];
        }
    }
    __syncthreads();
    if (tid < 128)
        logits[(size_t)row0 + tid] = s_red[tid][0] + s_red[tid][1] + __ldg(b2);
}

// ============================================================
// K2: per (batch, parcel) top-32 of z = logits + gumbel.
// ============================================================
__global__ void k_select(const float* __restrict__ logits,
                         const float* __restrict__ gumbel,
                         float* __restrict__ out_idx)
{
    const int g = blockIdx.x * (blockDim.x >> 5) + (threadIdx.x >> 5);
    const int lane = threadIdx.x & 31;
    const int b = g >> 6;
    const int p = g & 63;
    const float NEG_INF = __int_as_float(0xff800000);

    float v[4];
    int nidx[4];
#pragma unroll
    for (int q = 0; q < 4; q++) {
        int n = p + 64 * (lane + 32 * q);
        size_t off = (size_t)b * NN + n;
        v[q] = logits[off] + gumbel[off];
        nidx[q] = n;
    }

    for (int it = 0; it < KSEL; it++) {
        float bv = v[0]; int bn = nidx[0];
#pragma unroll
        for (int q = 1; q < 4; q++)
            if (v[q] > bv || (v[q] == bv && nidx[q] < bn)) { bv = v[q]; bn = nidx[q]; }
#pragma unroll
        for (int off = 16; off; off >>= 1) {
            float ov = __shfl_xor_sync(0xFFFFFFFFu, bv, off);
            int   on = __shfl_xor_sync(0xFFFFFFFFu, bn, off);
            if (ov > bv || (ov == bv && on < bn)) { bv = ov; bn = on; }
        }
        if (lane == 0)
            out_idx[(size_t)b * SEL_PER_B + p * KSEL + it] = (float)bn;
#pragma unroll
        for (int q = 0; q < 4; q++)
            if (nidx[q] == bn) v[q] = NEG_INF;
    }
}

// ============================================================
// K3: gather selected patch rows (warp per row).
// ============================================================
__global__ __launch_bounds__(256)
void k_gather(const float* __restrict__ patches,
              const float* __restrict__ out_idx,
              float* __restrict__ out_sel)
{
    const int gw = blockIdx.x * 8 + (threadIdx.x >> 5);
    const int lane = threadIdx.x & 31;
    const int b = gw >> 11;
    const int j = gw & 2047;
    const int n = (int)out_idx[(size_t)b * SEL_PER_B + j];
    const float4* src = (const float4*)&patches[((size_t)b * NN + n) * DD];
    float4* dst = (float4*)&out_sel[((size_t)b * SEL_PER_B + j) * DD];
    dst[lane]      = src[lane];
    dst[lane + 32] = src[lane + 32];
}

// ============================================================
// launch
// ============================================================
extern "C" void kernel_launch(void* const* d_in, const int* in_sizes, int n_in,
                              void* d_out, int out_size)
{
    const float* patches  = (const float*)d_in[0];
    const float* features = (const float*)d_in[1];
    const float* W1       = (const float*)d_in[2];
    const float* b1       = (const float*)d_in[3];
    const float* W2       = (const float*)d_in[4];
    const float* b2       = (const float*)d_in[5];
    const float* gumbel   = (const float*)d_in[6];

    float* out      = (float*)d_out;
    float* out_sel  = out;                                 // [B, 2048, 256]
    float* out_idx  = out + (size_t)BB * SEL_PER_B * DD;   // [B, 2048]
    float* out_log  = out_idx + (size_t)BB * SEL_PER_B;    // [B, N]

    k_prepB<<<64, 256>>>(W1);
    k_logits_tc<<<ROWS / 128, 128>>>(features, b1, W2, b2, out_log);
    k_select<<<(BB * NP) / 8, 256>>>(out_log, gumbel, out_idx);
    k_gather<<<BB * SEL_PER_B / 8, 256>>>(patches, out_idx, out_sel);
}

// round 8
// speedup vs baseline: 1.2413x; 1.0501x over previous
#include <cuda_runtime.h>
#include <cuda_bf16.h>
#include <stdint.h>

// Problem constants
#define BB 16
#define NN 8192
#define DD 256
#define HH 128
#define NP 64
#define KSEL 32
#define ROWS (BB * NN)          // 131072
#define SEL_PER_B (NP * KSEL)   // 2048

// ---- bf16 pack/extract helpers ----
__device__ __forceinline__ uint32_t pack_bf16x2(float x, float y) {
    uint32_t r;
    asm("cvt.rn.bf16x2.f32 %0, %1, %2;" : "=r"(r) : "f"(y), "f"(x));
    return r;
}
__device__ __forceinline__ float bf_lo(uint32_t p) { return __uint_as_float(p << 16); }
__device__ __forceinline__ float bf_hi(uint32_t p) { return __uint_as_float(p & 0xFFFF0000u); }

__device__ __forceinline__ void mma_bf16(float c[4],
                                         uint32_t a0, uint32_t a1, uint32_t a2, uint32_t a3,
                                         uint32_t b0, uint32_t b1) {
    asm volatile(
        "mma.sync.aligned.m16n8k16.row.col.f32.bf16.bf16.f32 "
        "{%0,%1,%2,%3}, {%4,%5,%6,%7}, {%8,%9}, {%0,%1,%2,%3};"
        : "+f"(c[0]), "+f"(c[1]), "+f"(c[2]), "+f"(c[3])
        : "r"(a0), "r"(a1), "r"(a2), "r"(a3), "r"(b0), "r"(b1));
}

__device__ __forceinline__ uint32_t smem_u32(const void* p) {
    uint32_t a;
    asm("{ .reg .u64 t; cvta.to.shared.u64 t, %1; cvt.u32.u64 %0, t; }" : "=r"(a) : "l"(p));
    return a;
}
__device__ __forceinline__ void cp_async16(uint32_t dst, const void* src) {
    asm volatile("cp.async.cg.shared.global [%0], [%1], 16;" :: "r"(dst), "l"(src));
}
__device__ __forceinline__ void cp_async8(uint32_t dst, const void* src) {
    asm volatile("cp.async.ca.shared.global [%0], [%1], 8;" :: "r"(dst), "l"(src));
}
#define CP_COMMIT() asm volatile("cp.async.commit_group;")
#define CP_WAIT0()  asm volatile("cp.async.wait_group 0;")

// W1 split into 2 bf16 planes, mma B-fragment layout:
// g_Bf[kt][nt][plane][lane] = uint2 {b0, b1}
__device__ uint2 g_Bf[16][16][2][32];

// ============================================================
// K0: build split W1 fragment table
// ============================================================
__global__ void k_prepB(const float* __restrict__ W1)
{
    int idx  = blockIdx.x * 256 + threadIdx.x;   // 0..16383
    int lane = idx & 31;
    int pl   = (idx >> 5) & 1;
    int nt   = (idx >> 6) & 15;
    int kt   = idx >> 10;

    int k0 = kt * 16 + (lane & 3) * 2;
    int n  = nt * 8 + (lane >> 2);

    uint32_t reg[2];
#pragma unroll
    for (int r = 0; r < 2; r++) {
        int k = k0 + r * 8;
        float v0 = W1[(size_t)k * HH + n];
        float v1 = W1[(size_t)(k + 1) * HH + n];
        uint32_t h = pack_bf16x2(v0, v1);
        reg[r] = (pl == 0) ? h : pack_bf16x2(v0 - bf_lo(h), v1 - bf_hi(h));
    }
    g_Bf[kt][nt][pl][lane] = make_uint2(reg[0], reg[1]);
}

// ============================================================
// K1: logits = relu(features @ W1 + b1) @ W2 + b2
// Split-bf16 mma.sync (4 products), product-outer MMA ordering
// so consecutive MMAs hit distinct accumulators (RAW distance 32).
// CTA: 128x128, 4 warps (2wm x 2wn), warp tile 64x64.
// A and B double-buffered in smem via cp.async.
// ============================================================
#define ASTRIDE 18   // floats per A smem row

__global__ __launch_bounds__(128, 2)
void k_logits_tc(const float* __restrict__ features,
                 const float* __restrict__ b1,
                 const float* __restrict__ W2,
                 const float* __restrict__ b2,
                 float* __restrict__ logits)
{
    __shared__ float sA[2][128][ASTRIDE];
    __shared__ uint2 sB[2][16][2][32];
    __shared__ float s_b1[HH], s_w2[HH];
    __shared__ float s_red[128][2];

    const int tid  = threadIdx.x;
    const int wid  = tid >> 5;
    const int lane = tid & 31;
    const int wm   = wid >> 1;       // 0..1
    const int wn   = wid & 1;        // 0..1
    const int g    = lane >> 2;      // 0..7
    const int tig  = lane & 3;       // 0..3
    const int row0 = blockIdx.x * 128;

    if (tid < HH) { s_b1[tid] = b1[tid]; s_w2[tid] = W2[tid]; }

    const float* Abase = features + (size_t)row0 * DD;

    auto prefetch = [&](int stage, int kt) {
        const int koff = kt * 16;
#pragma unroll
        for (int i = 0; i < 8; i++) {
            int cidx = tid + 128 * i;
            int r = cidx >> 3;
            int c = cidx & 7;
            cp_async8(smem_u32(&sA[stage][r][c * 2]),
                      Abase + (size_t)r * DD + koff + c * 2);
        }
        const char* src = (const char*)&g_Bf[kt][0][0][0];
        uint32_t dst = smem_u32(&sB[stage][0][0][0]);
#pragma unroll
        for (int i = 0; i < 4; i++) {
            int c = tid + 128 * i;
            cp_async16(dst + c * 16, src + c * 16);
        }
        CP_COMMIT();
    };

    prefetch(0, 0);

    float acc[4][8][4];
#pragma unroll
    for (int mt = 0; mt < 4; mt++)
#pragma unroll
        for (int nt = 0; nt < 8; nt++)
#pragma unroll
            for (int c = 0; c < 4; c++) acc[mt][nt][c] = 0.0f;

    const int rg = wm * 64 + g;
    const int kcol = tig * 2;

    for (int kt = 0; kt < 16; kt++) {
        const int buf = kt & 1;
        CP_WAIT0();
        __syncthreads();
        if (kt < 15) prefetch(buf ^ 1, kt + 1);

        // load all B fragments for this warp's 8 nt tiles
        uint2 bh[8], bl[8];
#pragma unroll
        for (int nt = 0; nt < 8; nt++) {
            const int ntg = wn * 8 + nt;
            bh[nt] = sB[buf][ntg][0][lane];
            bl[nt] = sB[buf][ntg][1][lane];
        }

        // convert A from smem to split fragments
        uint32_t Ah[4][4], Al[4][4];
#pragma unroll
        for (int mt = 0; mt < 4; mt++) {
            const int r0 = rg + mt * 16;
            float2 v00 = *(const float2*)&sA[buf][r0][kcol];
            float2 v10 = *(const float2*)&sA[buf][r0 + 8][kcol];
            float2 v01 = *(const float2*)&sA[buf][r0][kcol + 8];
            float2 v11 = *(const float2*)&sA[buf][r0 + 8][kcol + 8];
            Ah[mt][0] = pack_bf16x2(v00.x, v00.y);
            Ah[mt][1] = pack_bf16x2(v10.x, v10.y);
            Ah[mt][2] = pack_bf16x2(v01.x, v01.y);
            Ah[mt][3] = pack_bf16x2(v11.x, v11.y);
            Al[mt][0] = pack_bf16x2(v00.x - bf_lo(Ah[mt][0]), v00.y - bf_hi(Ah[mt][0]));
            Al[mt][1] = pack_bf16x2(v10.x - bf_lo(Ah[mt][1]), v10.y - bf_hi(Ah[mt][1]));
            Al[mt][2] = pack_bf16x2(v01.x - bf_lo(Ah[mt][2]), v01.y - bf_hi(Ah[mt][2]));
            Al[mt][3] = pack_bf16x2(v11.x - bf_lo(Ah[mt][3]), v11.y - bf_hi(Ah[mt][3]));
        }

        // product-outer: 4 passes of 32 independent MMAs
#pragma unroll
        for (int nt = 0; nt < 8; nt++)
#pragma unroll
            for (int mt = 0; mt < 4; mt++)
                mma_bf16(acc[mt][nt], Ah[mt][0], Ah[mt][1], Ah[mt][2], Ah[mt][3], bh[nt].x, bh[nt].y);
#pragma unroll
        for (int nt = 0; nt < 8; nt++)
#pragma unroll
            for (int mt = 0; mt < 4; mt++)
                mma_bf16(acc[mt][nt], Ah[mt][0], Ah[mt][1], Ah[mt][2], Ah[mt][3], bl[nt].x, bl[nt].y);
#pragma unroll
        for (int nt = 0; nt < 8; nt++)
#pragma unroll
            for (int mt = 0; mt < 4; mt++)
                mma_bf16(acc[mt][nt], Al[mt][0], Al[mt][1], Al[mt][2], Al[mt][3], bh[nt].x, bh[nt].y);
#pragma unroll
        for (int nt = 0; nt < 8; nt++)
#pragma unroll
            for (int mt = 0; mt < 4; mt++)
                mma_bf16(acc[mt][nt], Al[mt][0], Al[mt][1], Al[mt][2], Al[mt][3], bl[nt].x, bl[nt].y);
    }

    // Epilogue: relu(c + b1) * W2, reduce over hidden
    float rs[8];
#pragma unroll
    for (int i = 0; i < 8; i++) rs[i] = 0.0f;
#pragma unroll
    for (int nt = 0; nt < 8; nt++) {
        const int c = wn * 64 + nt * 8 + tig * 2;
        float bb0 = s_b1[c],     w0 = s_w2[c];
        float bb1 = s_b1[c + 1], w1 = s_w2[c + 1];
#pragma unroll
        for (int mt = 0; mt < 4; mt++) {
            float x0 = acc[mt][nt][0] + bb0; x0 = x0 > 0.0f ? x0 : 0.0f;
            float x1 = acc[mt][nt][1] + bb1; x1 = x1 > 0.0f ? x1 : 0.0f;
            float x2 = acc[mt][nt][2] + bb0; x2 = x2 > 0.0f ? x2 : 0.0f;
            float x3 = acc[mt][nt][3] + bb1; x3 = x3 > 0.0f ? x3 : 0.0f;
            rs[2 * mt + 0] += x0 * w0 + x1 * w1;
            rs[2 * mt + 1] += x2 * w0 + x3 * w1;
        }
    }
#pragma unroll
    for (int off = 1; off <= 2; off <<= 1)
#pragma unroll
        for (int i = 0; i < 8; i++)
            rs[i] += __shfl_xor_sync(0xFFFFFFFFu, rs[i], off);

    if (tig == 0) {
#pragma unroll
        for (int mt = 0; mt < 4; mt++) {
            s_red[wm * 64 + mt * 16 + g][wn]     = rs[2 * mt + 0];
            s_red[wm * 64 + mt * 16 + g + 8][wn] = rs[2 * mt + 1];
        }
    }
    __syncthreads();
    if (tid < 128)
        logits[(size_t)row0 + tid] = s_red[tid][0] + s_red[tid][1] + __ldg(b2);
}

// ============================================================
// K2: per (batch, parcel) top-32 of z = logits + gumbel.
// ============================================================
__global__ void k_select(const float* __restrict__ logits,
                         const float* __restrict__ gumbel,
                         float* __restrict__ out_idx)
{
    const int g = blockIdx.x * (blockDim.x >> 5) + (threadIdx.x >> 5);
    const int lane = threadIdx.x & 31;
    const int b = g >> 6;
    const int p = g & 63;
    const float NEG_INF = __int_as_float(0xff800000);

    float v[4];
    int nidx[4];
#pragma unroll
    for (int q = 0; q < 4; q++) {
        int n = p + 64 * (lane + 32 * q);
        size_t off = (size_t)b * NN + n;
        v[q] = logits[off] + gumbel[off];
        nidx[q] = n;
    }

    for (int it = 0; it < KSEL; it++) {
        float bv = v[0]; int bn = nidx[0];
#pragma unroll
        for (int q = 1; q < 4; q++)
            if (v[q] > bv || (v[q] == bv && nidx[q] < bn)) { bv = v[q]; bn = nidx[q]; }
#pragma unroll
        for (int off = 16; off; off >>= 1) {
            float ov = __shfl_xor_sync(0xFFFFFFFFu, bv, off);
            int   on = __shfl_xor_sync(0xFFFFFFFFu, bn, off);
            if (ov > bv || (ov == bv && on < bn)) { bv = ov; bn = on; }
        }
        if (lane == 0)
            out_idx[(size_t)b * SEL_PER_B + p * KSEL + it] = (float)bn;
#pragma unroll
        for (int q = 0; q < 4; q++)
            if (nidx[q] == bn) v[q] = NEG_INF;
    }
}

// ============================================================
// K3: gather selected patch rows (warp per row).
// ============================================================
__global__ __launch_bounds__(256)
void k_gather(const float* __restrict__ patches,
              const float* __restrict__ out_idx,
              float* __restrict__ out_sel)
{
    const int gw = blockIdx.x * 8 + (threadIdx.x >> 5);
    const int lane = threadIdx.x & 31;
    const int b = gw >> 11;
    const int j = gw & 2047;
    const int n = (int)out_idx[(size_t)b * SEL_PER_B + j];
    const float4* src = (const float4*)&patches[((size_t)b * NN + n) * DD];
    float4* dst = (float4*)&out_sel[((size_t)b * SEL_PER_B + j) * DD];
    dst[lane]      = src[lane];
    dst[lane + 32] = src[lane + 32];
}

// ============================================================
// launch
// ============================================================
extern "C" void kernel_launch(void* const* d_in, const int* in_sizes, int n_in,
                              void* d_out, int out_size)
{
    const float* patches  = (const float*)d_in[0];
    const float* features = (const float*)d_in[1];
    const float* W1       = (const float*)d_in[2];
    const float* b1       = (const float*)d_in[3];
    const float* W2       = (const float*)d_in[4];
    const float* b2       = (const float*)d_in[5];
    const float* gumbel   = (const float*)d_in[6];

    float* out      = (float*)d_out;
    float* out_sel  = out;                                 // [B, 2048, 256]
    float* out_idx  = out + (size_t)BB * SEL_PER_B * DD;   // [B, 2048]
    float* out_log  = out_idx + (size_t)BB * SEL_PER_B;    // [B, N]

    k_prepB<<<64, 256>>>(W1);
    k_logits_tc<<<ROWS / 128, 128>>>(features, b1, W2, b2, out_log);
    k_select<<<(BB * NP) / 8, 256>>>(out_log, gumbel, out_idx);
    k_gather<<<BB * SEL_PER_B / 8, 256>>>(patches, out_idx, out_sel);
}